// round 1
// baseline (speedup 1.0000x reference)
#include <cuda_runtime.h>

// ChamferDistance: x,y = [16, 4096, 3] fp32 -> scalar
//   ref: mean_b [ mean_i min_j d(x_i,y_j) + mean_j min_i d(x_i,y_j) ]
//   d computed via norm expansion (matches reference numerics):
//   d = x2 + y2 - 2 x.y  ->  per-pair t = y2_j - 2 x.y_j ; add x2_i after min.

#define NB      16
#define NPTS    4096
#define SPLITS  8
#define QPB     (NPTS / SPLITS)   // 512 query points per block
#define THREADS 128
#define PPT     (QPB / THREADS)   // 4 query points per thread
#define NBLOCKS (NB * 2 * SPLITS) // 256

__device__ float g_partial[NBLOCKS];

__global__ __launch_bounds__(THREADS) void chamfer_kernel(
    const float* __restrict__ x, const float* __restrict__ y)
{
    extern __shared__ float4 sdb[];   // [NPTS] : (d0, d1, d2, d0^2+d1^2+d2^2)

    const int dir = blockIdx.y;       // 0: query=x, db=y ; 1: query=y, db=x
    const int b   = blockIdx.z;
    const float* __restrict__ q  = (dir ? y : x) + (size_t)b * NPTS * 3;
    const float* __restrict__ db = (dir ? x : y) + (size_t)b * NPTS * 3;

    // Cooperative load of the full db side into shared, with precomputed |p|^2.
    for (int j = threadIdx.x; j < NPTS; j += THREADS) {
        float a = db[3 * j + 0];
        float c = db[3 * j + 1];
        float d = db[3 * j + 2];
        sdb[j] = make_float4(a, c, d, fmaf(a, a, fmaf(c, c, d * d)));
    }
    __syncthreads();

    // Per-thread query points (4 consecutive), precompute -2x and |x|^2.
    float n0[PPT], n1[PPT], n2[PPT], q2[PPT], m[PPT];
    const int qbase = blockIdx.x * QPB + threadIdx.x * PPT;
#pragma unroll
    for (int p = 0; p < PPT; p++) {
        float a = q[3 * (qbase + p) + 0];
        float c = q[3 * (qbase + p) + 1];
        float d = q[3 * (qbase + p) + 2];
        n0[p] = -2.0f * a;
        n1[p] = -2.0f * c;
        n2[p] = -2.0f * d;
        q2[p] = fmaf(a, a, fmaf(c, c, d * d));
        m[p]  = 3.402823466e+38f;
    }

    // Main loop: 1 LDS.128 (broadcast) + 12 FFMA + 4 FMNMX per db point per warp.
#pragma unroll 4
    for (int j = 0; j < NPTS; j++) {
        const float4 v = sdb[j];
#pragma unroll
        for (int p = 0; p < PPT; p++) {
            float t = fmaf(n0[p], v.x, v.w);
            t = fmaf(n1[p], v.y, t);
            t = fmaf(n2[p], v.z, t);
            m[p] = fminf(m[p], t);
        }
    }

    // Per-thread sum of nearest-neighbor squared distances (+x2 term).
    float s = 0.0f;
#pragma unroll
    for (int p = 0; p < PPT; p++) s += m[p] + q2[p];

    // Warp reduce (fixed shuffle order -> deterministic)
#pragma unroll
    for (int o = 16; o > 0; o >>= 1) s += __shfl_down_sync(0xFFFFFFFFu, s, o);

    __shared__ float red[THREADS / 32];
    if ((threadIdx.x & 31) == 0) red[threadIdx.x >> 5] = s;
    __syncthreads();
    if (threadIdx.x == 0) {
        float t = 0.0f;
#pragma unroll
        for (int w = 0; w < THREADS / 32; w++) t += red[w];
        const int lin = blockIdx.x + SPLITS * (blockIdx.y + 2 * blockIdx.z);
        g_partial[lin] = t;
    }
}

__global__ void final_reduce_kernel(float* __restrict__ out)
{
    __shared__ float s[NBLOCKS];
    const int i = threadIdx.x;
    s[i] = g_partial[i];
    __syncthreads();
#pragma unroll
    for (int o = NBLOCKS / 2; o > 0; o >>= 1) {
        if (i < o) s[i] += s[i + o];
        __syncthreads();
    }
    if (i == 0) out[0] = s[0] * (1.0f / ((float)NB * (float)NPTS));
}

extern "C" void kernel_launch(void* const* d_in, const int* in_sizes, int n_in,
                              void* d_out, int out_size)
{
    const float* x = (const float*)d_in[0];
    const float* y = (const float*)d_in[1];
    float* out = (float*)d_out;

    const int smem = NPTS * sizeof(float4);  // 64 KB
    cudaFuncSetAttribute(chamfer_kernel,
                         cudaFuncAttributeMaxDynamicSharedMemorySize, smem);

    dim3 grid(SPLITS, 2, NB);
    chamfer_kernel<<<grid, THREADS, smem>>>(x, y);
    final_reduce_kernel<<<1, NBLOCKS>>>(out);
}

// round 2
// speedup vs baseline: 1.1796x; 1.1796x over previous
#include <cuda_runtime.h>

// ChamferDistance: x,y = [16, 4096, 3] fp32 -> scalar
//   d = x2 + y2 - 2 x.y ; per-pair t = y2_j - 2 x.y_j ; add x2_i after min.
// R2: packed fma.rn.f32x2 over pairs of db points (FFMA2 halves FMA-pipe work),
//     SoA shared layout so packed db operands come straight from LDS.128.

#define NB      16
#define NPTS    4096
#define SPLITS  8
#define QPB     (NPTS / SPLITS)   // 512 query points per block
#define THREADS 128
#define PPT     (QPB / THREADS)   // 4 query points per thread
#define NBLOCKS (NB * 2 * SPLITS) // 256

__device__ float g_partial[NBLOCKS];

typedef unsigned long long ull;

__device__ __forceinline__ ull pack2(float a, float b) {
    ull r; asm("mov.b64 %0, {%1, %2};" : "=l"(r) : "f"(a), "f"(b)); return r;
}
__device__ __forceinline__ ull fma2(ull a, ull b, ull c) {
    ull d; asm("fma.rn.f32x2 %0, %1, %2, %3;" : "=l"(d) : "l"(a), "l"(b), "l"(c)); return d;
}
__device__ __forceinline__ void unpack2(ull v, float& lo, float& hi) {
    asm("mov.b64 {%0, %1}, %2;" : "=f"(lo), "=f"(hi) : "l"(v));
}

__global__ __launch_bounds__(THREADS) void chamfer_kernel(
    const float* __restrict__ x, const float* __restrict__ y)
{
    extern __shared__ float smem[];
    float* __restrict__ sx = smem;               // [NPTS]
    float* __restrict__ sy = smem + NPTS;        // [NPTS]
    float* __restrict__ sz = smem + 2 * NPTS;    // [NPTS]
    float* __restrict__ sw = smem + 3 * NPTS;    // [NPTS]  |p|^2

    const int dir = blockIdx.y;       // 0: query=x, db=y ; 1: query=y, db=x
    const int b   = blockIdx.z;
    const float* __restrict__ q  = (dir ? y : x) + (size_t)b * NPTS * 3;
    const float* __restrict__ db = (dir ? x : y) + (size_t)b * NPTS * 3;

    // Cooperative SoA load of db side + precomputed |p|^2.
    for (int j = threadIdx.x; j < NPTS; j += THREADS) {
        float a = db[3 * j + 0];
        float c = db[3 * j + 1];
        float d = db[3 * j + 2];
        sx[j] = a; sy[j] = c; sz[j] = d;
        sw[j] = fmaf(a, a, fmaf(c, c, d * d));
    }
    __syncthreads();

    // Per-thread query points: packed duplicated coefficients {-2x, -2x}.
    ull n0[PPT], n1[PPT], n2[PPT];
    float q2[PPT], m0[PPT], m1[PPT];
    const int qbase = blockIdx.x * QPB + threadIdx.x * PPT;
#pragma unroll
    for (int p = 0; p < PPT; p++) {
        float a = q[3 * (qbase + p) + 0];
        float c = q[3 * (qbase + p) + 1];
        float d = q[3 * (qbase + p) + 2];
        n0[p] = pack2(-2.0f * a, -2.0f * a);
        n1[p] = pack2(-2.0f * c, -2.0f * c);
        n2[p] = pack2(-2.0f * d, -2.0f * d);
        q2[p] = fmaf(a, a, fmaf(c, c, d * d));
        m0[p] = 3.402823466e+38f;
        m1[p] = 3.402823466e+38f;
    }

    // Main loop: per 4 db points, 4x LDS.128 + 24 FFMA2 + 16 FMNMX.
#pragma unroll 2
    for (int j = 0; j < NPTS; j += 4) {
        const float4 X = *(const float4*)(sx + j);
        const float4 Y = *(const float4*)(sy + j);
        const float4 Z = *(const float4*)(sz + j);
        const float4 W = *(const float4*)(sw + j);
        const ull Xa = pack2(X.x, X.y), Xb = pack2(X.z, X.w);
        const ull Ya = pack2(Y.x, Y.y), Yb = pack2(Y.z, Y.w);
        const ull Za = pack2(Z.x, Z.y), Zb = pack2(Z.z, Z.w);
        const ull Wa = pack2(W.x, W.y), Wb = pack2(W.z, W.w);
#pragma unroll
        for (int p = 0; p < PPT; p++) {
            ull ta = fma2(n0[p], Xa, Wa);
            ta = fma2(n1[p], Ya, ta);
            ta = fma2(n2[p], Za, ta);
            float a0, a1; unpack2(ta, a0, a1);
            m0[p] = fminf(m0[p], a0);
            m1[p] = fminf(m1[p], a1);

            ull tb = fma2(n0[p], Xb, Wb);
            tb = fma2(n1[p], Yb, tb);
            tb = fma2(n2[p], Zb, tb);
            float b0, b1; unpack2(tb, b0, b1);
            m0[p] = fminf(m0[p], b0);
            m1[p] = fminf(m1[p], b1);
        }
    }

    // Per-thread sum of NN sq-dists (+ |q|^2 term).
    float s = 0.0f;
#pragma unroll
    for (int p = 0; p < PPT; p++) s += fminf(m0[p], m1[p]) + q2[p];

    // Warp reduce (fixed shuffle order -> deterministic)
#pragma unroll
    for (int o = 16; o > 0; o >>= 1) s += __shfl_down_sync(0xFFFFFFFFu, s, o);

    __shared__ float red[THREADS / 32];
    if ((threadIdx.x & 31) == 0) red[threadIdx.x >> 5] = s;
    __syncthreads();
    if (threadIdx.x == 0) {
        float t = 0.0f;
#pragma unroll
        for (int w = 0; w < THREADS / 32; w++) t += red[w];
        const int lin = blockIdx.x + SPLITS * (blockIdx.y + 2 * blockIdx.z);
        g_partial[lin] = t;
    }
}

__global__ void final_reduce_kernel(float* __restrict__ out)
{
    __shared__ float s[NBLOCKS];
    const int i = threadIdx.x;
    s[i] = g_partial[i];
    __syncthreads();
#pragma unroll
    for (int o = NBLOCKS / 2; o > 0; o >>= 1) {
        if (i < o) s[i] += s[i + o];
        __syncthreads();
    }
    if (i == 0) out[0] = s[0] * (1.0f / ((float)NB * (float)NPTS));
}

extern "C" void kernel_launch(void* const* d_in, const int* in_sizes, int n_in,
                              void* d_out, int out_size)
{
    const float* x = (const float*)d_in[0];
    const float* y = (const float*)d_in[1];
    float* out = (float*)d_out;

    const int smem = 4 * NPTS * sizeof(float);  // 64 KB SoA
    cudaFuncSetAttribute(chamfer_kernel,
                         cudaFuncAttributeMaxDynamicSharedMemorySize, smem);

    dim3 grid(SPLITS, 2, NB);
    chamfer_kernel<<<grid, THREADS, smem>>>(x, y);
    final_reduce_kernel<<<1, NBLOCKS>>>(out);
}

// round 3
// speedup vs baseline: 1.2085x; 1.0245x over previous
#include <cuda_runtime.h>

// ChamferDistance: x,y = [16, 4096, 3] fp32 -> scalar
// d = x2 + y2 - 2 x.y ; per-pair t = y2_j - 2 x.y_j ; add x2_i after min.
// R3: no pack MOVs (shared SoA read directly as ulonglong2 -> native f32x2
//     operands), final reduction folded into main kernel (ticket counter).

#define NB      16
#define NPTS    4096
#define SPLITS  8
#define QPB     (NPTS / SPLITS)   // 512 query points per block
#define THREADS 128
#define PPT     (QPB / THREADS)   // 4 query points per thread
#define NBLOCKS (NB * 2 * SPLITS) // 256

__device__ float g_partial[NBLOCKS];
__device__ unsigned int g_ticket;   // zero-initialized; reset by last block

typedef unsigned long long ull;

__device__ __forceinline__ ull pack2(float a, float b) {
    ull r; asm("mov.b64 %0, {%1, %2};" : "=l"(r) : "f"(a), "f"(b)); return r;
}
__device__ __forceinline__ ull fma2(ull a, ull b, ull c) {
    ull d; asm("fma.rn.f32x2 %0, %1, %2, %3;" : "=l"(d) : "l"(a), "l"(b), "l"(c)); return d;
}
__device__ __forceinline__ void unpack2(ull v, float& lo, float& hi) {
    asm("mov.b64 {%0, %1}, %2;" : "=f"(lo), "=f"(hi) : "l"(v));
}

__global__ __launch_bounds__(THREADS) void chamfer_kernel(
    const float* __restrict__ x, const float* __restrict__ y,
    float* __restrict__ out)
{
    extern __shared__ float smem[];
    float* __restrict__ sx = smem;               // [NPTS]
    float* __restrict__ sy = smem + NPTS;        // [NPTS]
    float* __restrict__ sz = smem + 2 * NPTS;    // [NPTS]
    float* __restrict__ sw = smem + 3 * NPTS;    // [NPTS]  |p|^2

    const int dir = blockIdx.y;       // 0: query=x, db=y ; 1: query=y, db=x
    const int b   = blockIdx.z;
    const float* __restrict__ q  = (dir ? y : x) + (size_t)b * NPTS * 3;
    const float* __restrict__ db = (dir ? x : y) + (size_t)b * NPTS * 3;

    // Cooperative SoA load of db side + precomputed |p|^2.
    for (int j = threadIdx.x; j < NPTS; j += THREADS) {
        float a = db[3 * j + 0];
        float c = db[3 * j + 1];
        float d = db[3 * j + 2];
        sx[j] = a; sy[j] = c; sz[j] = d;
        sw[j] = fmaf(a, a, fmaf(c, c, d * d));
    }
    __syncthreads();

    // Per-thread query points: packed duplicated coefficients {-2q, -2q}
    // (built once outside the hot loop; cost negligible).
    ull n0[PPT], n1[PPT], n2[PPT];
    float q2[PPT], m0[PPT], m1[PPT];
    const int qbase = blockIdx.x * QPB + threadIdx.x * PPT;
#pragma unroll
    for (int p = 0; p < PPT; p++) {
        float a = q[3 * (qbase + p) + 0];
        float c = q[3 * (qbase + p) + 1];
        float d = q[3 * (qbase + p) + 2];
        n0[p] = pack2(-2.0f * a, -2.0f * a);
        n1[p] = pack2(-2.0f * c, -2.0f * c);
        n2[p] = pack2(-2.0f * d, -2.0f * d);
        q2[p] = fmaf(a, a, fmaf(c, c, d * d));
        m0[p] = 3.402823466e+38f;
        m1[p] = 3.402823466e+38f;
    }

    // Hot loop per 4 db points per thread:
    //   4x LDS.128 (each yields two pre-packed f32x2 operands, NO pack MOVs)
    //   24 FFMA2 + 16 FMNMX.
#pragma unroll 4
    for (int j = 0; j < NPTS; j += 4) {
        const ulonglong2 X = *(const ulonglong2*)(sx + j);
        const ulonglong2 Y = *(const ulonglong2*)(sy + j);
        const ulonglong2 Z = *(const ulonglong2*)(sz + j);
        const ulonglong2 W = *(const ulonglong2*)(sw + j);
#pragma unroll
        for (int p = 0; p < PPT; p++) {
            ull ta = fma2(n0[p], X.x, W.x);
            ta = fma2(n1[p], Y.x, ta);
            ta = fma2(n2[p], Z.x, ta);
            ull tb = fma2(n0[p], X.y, W.y);
            tb = fma2(n1[p], Y.y, tb);
            tb = fma2(n2[p], Z.y, tb);
            float a0, a1, b0, b1;
            unpack2(ta, a0, a1);
            unpack2(tb, b0, b1);
            m0[p] = fminf(m0[p], a0);
            m1[p] = fminf(m1[p], a1);
            m0[p] = fminf(m0[p], b0);
            m1[p] = fminf(m1[p], b1);
        }
    }

    // Per-thread sum of NN sq-dists (+ |q|^2 term).
    float s = 0.0f;
#pragma unroll
    for (int p = 0; p < PPT; p++) s += fminf(m0[p], m1[p]) + q2[p];

    // Warp reduce (fixed shuffle order -> deterministic)
#pragma unroll
    for (int o = 16; o > 0; o >>= 1) s += __shfl_down_sync(0xFFFFFFFFu, s, o);

    __shared__ float red[THREADS / 32];
    __shared__ bool amlast;
    if ((threadIdx.x & 31) == 0) red[threadIdx.x >> 5] = s;
    __syncthreads();
    if (threadIdx.x == 0) {
        float t = 0.0f;
#pragma unroll
        for (int w = 0; w < THREADS / 32; w++) t += red[w];
        const int lin = blockIdx.x + SPLITS * (blockIdx.y + 2 * blockIdx.z);
        g_partial[lin] = t;
        __threadfence();
        unsigned int old = atomicAdd(&g_ticket, 1u);
        amlast = (old == NBLOCKS - 1);
    }
    __syncthreads();

    // Last block reduces all partials in a fixed order (deterministic).
    if (amlast) {
        float v = 0.0f;
        if (threadIdx.x < NBLOCKS / PPT) {   // 64 threads, 4 each, fixed order
#pragma unroll
            for (int k = 0; k < PPT; k++)
                v += g_partial[threadIdx.x * PPT + k];
        }
#pragma unroll
        for (int o = 16; o > 0; o >>= 1) v += __shfl_down_sync(0xFFFFFFFFu, v, o);
        if ((threadIdx.x & 31) == 0) red[threadIdx.x >> 5] = v;
        __syncthreads();
        if (threadIdx.x == 0) {
            out[0] = (red[0] + red[1]) * (1.0f / ((float)NB * (float)NPTS));
            g_ticket = 0;   // reset for next graph replay
        }
    }
}

extern "C" void kernel_launch(void* const* d_in, const int* in_sizes, int n_in,
                              void* d_out, int out_size)
{
    const float* x = (const float*)d_in[0];
    const float* y = (const float*)d_in[1];
    float* out = (float*)d_out;

    const int smem = 4 * NPTS * sizeof(float);  // 64 KB SoA
    cudaFuncSetAttribute(chamfer_kernel,
                         cudaFuncAttributeMaxDynamicSharedMemorySize, smem);

    dim3 grid(SPLITS, 2, NB);
    chamfer_kernel<<<grid, THREADS, smem>>>(x, y, out);
}